// round 2
// baseline (speedup 1.0000x reference)
#include <cuda_runtime.h>

#define LL 512
#define IN_DIM 256
#define DM 32      // dim_msa
#define PD 64      // pairwise dim
#define CP 2048    // DM*PD

// Scratch (no allocations allowed in kernel_launch)
__device__ float g_x [LL * DM];      // x[i][d]
__device__ float g_xT[DM * LL];      // x transposed: [d][i]
__device__ float g_T [(size_t)LL * CP]; // T[i][c][p], 4 MB

// ---------------------------------------------------------------------------
// Kernel A: x = seq @ W1^T + b1   (512x256 @ 256x32)
// grid 64, block 256; each block does 8 rows of x.
// ---------------------------------------------------------------------------
__global__ void __launch_bounds__(256) k_proj1(const float* __restrict__ seq,
                                               const float* __restrict__ W1,
                                               const float* __restrict__ b1) {
    __shared__ __align__(16) float seqs[8][IN_DIM];     // 8 KB
    __shared__ __align__(16) float W1t[IN_DIM][DM];     // 32 KB, transposed
    const int tid = threadIdx.x;
    const int i0 = blockIdx.x * 8;

    #pragma unroll
    for (int t = 0; t < 32; ++t) {           // 8192 W1 elements
        int idx = t * 256 + tid;
        int d = idx >> 8, k = idx & 255;
        W1t[k][d] = W1[idx];
    }
    #pragma unroll
    for (int t = 0; t < 8; ++t) {            // 2048 seq elements
        int idx = t * 256 + tid;
        int r = idx >> 8, k = idx & 255;
        seqs[r][k] = seq[(i0 + r) * IN_DIM + k];
    }
    __syncthreads();

    const int r = tid >> 5, d = tid & 31;
    float acc = b1[d];
    #pragma unroll 8
    for (int k = 0; k < IN_DIM; ++k)
        acc = fmaf(seqs[r][k], W1t[k][d], acc);

    const int i = i0 + r;
    g_x[i * DM + d]  = acc;
    g_xT[d * LL + i] = acc;
}

// ---------------------------------------------------------------------------
// Kernel B: T[i][c][p] = sum_d x[i][d] * W2[p][c*32+d]
// GEMM M=512(i) x N=2048(cp=c*64+p) x K=32.
// grid (8 cp-tiles of 256, 16 i-tiles of 32), block 256, thread tile 4i x 8cp.
// ---------------------------------------------------------------------------
__global__ void __launch_bounds__(256) k_proj2(const float* __restrict__ W2) {
    __shared__ __align__(16) float ws[DM][256];  // [k][cp_local], 32 KB
    __shared__ __align__(16) float xs[DM][32];   // [k][i_local],   4 KB
    const int tid = threadIdx.x;
    const int cp0 = blockIdx.x * 256;
    const int i0  = blockIdx.y * 32;

    #pragma unroll
    for (int t = 0; t < 32; ++t) {           // 8192 W2 elements
        int idx = t * 256 + tid;
        int cpl = idx >> 5, k = idx & 31;
        int cp = cp0 + cpl;
        ws[k][cpl] = W2[(cp & 63) * 1024 + (cp >> 6) * 32 + k];
    }
    #pragma unroll
    for (int t = 0; t < 4; ++t) {            // 1024 x elements
        int idx = t * 256 + tid;
        int k = idx >> 5, il = idx & 31;
        xs[k][il] = g_xT[k * LL + i0 + il];
    }
    __syncthreads();

    const int cg = tid & 31;   // 8 consecutive cp per thread
    const int ig = tid >> 5;   // 4 consecutive i per thread
    float acc[4][8];
    #pragma unroll
    for (int a = 0; a < 4; ++a)
        #pragma unroll
        for (int b = 0; b < 8; ++b) acc[a][b] = 0.f;

    #pragma unroll 4
    for (int k = 0; k < DM; ++k) {
        float4 xv = *(const float4*)&xs[k][ig * 4];
        float4 wa = *(const float4*)&ws[k][cg * 8];
        float4 wb = *(const float4*)&ws[k][cg * 8 + 4];
        float xr[4] = {xv.x, xv.y, xv.z, xv.w};
        float wv[8] = {wa.x, wa.y, wa.z, wa.w, wb.x, wb.y, wb.z, wb.w};
        #pragma unroll
        for (int a = 0; a < 4; ++a)
            #pragma unroll
            for (int b = 0; b < 8; ++b)
                acc[a][b] = fmaf(xr[a], wv[b], acc[a][b]);
    }

    #pragma unroll
    for (int a = 0; a < 4; ++a) {
        float* dst = &g_T[(size_t)(i0 + ig * 4 + a) * CP + cp0 + cg * 8];
        *(float4*)(dst)     = make_float4(acc[a][0], acc[a][1], acc[a][2], acc[a][3]);
        *(float4*)(dst + 4) = make_float4(acc[a][4], acc[a][5], acc[a][6], acc[a][7]);
    }
}

// ---------------------------------------------------------------------------
// Kernel C: out[i][j][p] = b2[p] + sum_c x[j][c] * T[i][c][p]
// grid (2 j-tiles of 256, 512 i), block 256.
// Thread tile 8j x 8p, accumulated as 8j x 4 packed-f32x2 via fma.rn.f32x2.
// ---------------------------------------------------------------------------
__global__ void __launch_bounds__(256) k_outer(const float* __restrict__ b2,
                                               float* __restrict__ out) {
    __shared__ __align__(16) float Ts[DM][PD];    //  8 KB, [c][p]
    __shared__ __align__(16) float xs[DM][256];   // 32 KB, [c][j_local]
    const int tid = threadIdx.x;
    const int i  = blockIdx.y;
    const int j0 = blockIdx.x * 256;

    { // Ts: 2048 contiguous floats = 512 float4
        const float4* src = (const float4*)&g_T[(size_t)i * CP];
        float4* dst = (float4*)&Ts[0][0];
        dst[tid]       = src[tid];
        dst[tid + 256] = src[tid + 256];
    }
    #pragma unroll
    for (int t = 0; t < 32; ++t) {           // xs: 8192 floats (c = 0..31)
        int idx = t * 256 + tid;
        int c = idx >> 8, jl = idx & 255;
        xs[c][jl] = g_xT[c * LL + j0 + jl];
    }
    __syncthreads();

    const int lane = tid & 31, warp = tid >> 5;
    const int pg = lane >> 2;              // p-range: pg*8 .. pg*8+7
    const int jg = warp * 4 + (lane & 3);  // j-range: j0 + jg*8 .. +7

    unsigned long long acc2[8][4];
    { // init with bias pairs
        const float* bp = b2 + pg * 8;
        #pragma unroll
        for (int pp = 0; pp < 4; ++pp) {
            unsigned long long v;
            asm("mov.b64 %0, {%1, %2};" : "=l"(v) : "f"(bp[2 * pp]), "f"(bp[2 * pp + 1]));
            #pragma unroll
            for (int jj = 0; jj < 8; ++jj) acc2[jj][pp] = v;
        }
    }

    #pragma unroll 4
    for (int c = 0; c < DM; ++c) {
        float4 xa = *(const float4*)&xs[c][jg * 8];
        float4 xb = *(const float4*)&xs[c][jg * 8 + 4];
        ulonglong2 t01 = *(const ulonglong2*)&Ts[c][pg * 8];
        ulonglong2 t23 = *(const ulonglong2*)&Ts[c][pg * 8 + 4];
        unsigned long long tt[4] = {t01.x, t01.y, t23.x, t23.y};
        float xv[8] = {xa.x, xa.y, xa.z, xa.w, xb.x, xb.y, xb.z, xb.w};
        #pragma unroll
        for (int jj = 0; jj < 8; ++jj) {
            unsigned long long x2;
            asm("mov.b64 %0, {%1, %1};" : "=l"(x2) : "f"(xv[jj]));
            #pragma unroll
            for (int pp = 0; pp < 4; ++pp)
                asm("fma.rn.f32x2 %0, %1, %2, %0;"
                    : "+l"(acc2[jj][pp]) : "l"(x2), "l"(tt[pp]));
        }
    }

    #pragma unroll
    for (int jj = 0; jj < 8; ++jj) {
        size_t base = ((size_t)i * LL + j0 + jg * 8 + jj) * PD + pg * 8;
        *(ulonglong2*)&out[base]     = make_ulonglong2(acc2[jj][0], acc2[jj][1]);
        *(ulonglong2*)&out[base + 4] = make_ulonglong2(acc2[jj][2], acc2[jj][3]);
    }
}

// ---------------------------------------------------------------------------
extern "C" void kernel_launch(void* const* d_in, const int* in_sizes, int n_in,
                              void* d_out, int out_size) {
    const float* seq = (const float*)d_in[0];
    const float* W1  = (const float*)d_in[1];
    const float* b1  = (const float*)d_in[2];
    const float* W2  = (const float*)d_in[3];
    const float* b2  = (const float*)d_in[4];
    float* out = (float*)d_out;

    k_proj1<<<64, 256>>>(seq, W1, b1);
    k_proj2<<<dim3(8, 16), 256>>>(W2);
    k_outer<<<dim3(2, 512), 256>>>(b2, out);
}

// round 6
// speedup vs baseline: 1.2395x; 1.2395x over previous
#include <cuda_runtime.h>
#include <cuda_bf16.h>
#include <cstdint>

#define LL 512
#define IN_DIM 256
#define DM 32      // dim_msa (contraction dims c and d)
#define PD 64      // pairwise dim
#define CP 2048    // DM*PD

// ---------------------------------------------------------------------------
// Global scratch (no allocs allowed). mma.sync fragment layouts:
//   A frag (16x16 bf16, row-major): reg r of lane l holds rows/cols per PTX ISA.
//   g_Af_*[ ((mt*2+ks)*32 + lane)*4 + reg ]   mt=j>>4 (32), ks=c>>4 (2)   32 KB each
//   g_Bf_*[ i*1024 + ((nt*2+ks)*32 + lane)*2 + reg ]  nt=p>>3 (8)        2 MB each
// ---------------------------------------------------------------------------
__device__ __align__(16) unsigned g_Af_hi[8192];
__device__ __align__(16) unsigned g_Af_lo[8192];
__device__ __align__(16) unsigned g_Bf_hi[512 * 1024];
__device__ __align__(16) unsigned g_Bf_lo[512 * 1024];
__device__ float g_xT[DM * LL];          // x transposed: [d][i] (for k_proj2)

__device__ __forceinline__ unsigned pack_bf(__nv_bfloat16 lo16, __nv_bfloat16 hi16) {
    // low 16 bits = first (even-index) element
    return (unsigned)__bfloat16_as_ushort(lo16) |
           ((unsigned)__bfloat16_as_ushort(hi16) << 16);
}
__device__ __forceinline__ void split_bf(float f, __nv_bfloat16& h, __nv_bfloat16& l) {
    h = __float2bfloat16(f);
    l = __float2bfloat16(f - __bfloat162float(h));
}

// ---------------------------------------------------------------------------
// Kernel A: x = seq @ W1^T + b1 (512x256 @ 256x32); emits A-fragments (hi/lo)
// grid 64, block 256; each block does 8 rows of x.
// ---------------------------------------------------------------------------
__global__ void __launch_bounds__(256) k_proj1(const float* __restrict__ seq,
                                               const float* __restrict__ W1,
                                               const float* __restrict__ b1) {
    __shared__ __align__(16) float seqs[8][IN_DIM];
    __shared__ __align__(16) float W1t[IN_DIM][DM];
    const int tid = threadIdx.x;
    const int i0 = blockIdx.x * 8;

    #pragma unroll
    for (int t = 0; t < 32; ++t) {
        int idx = t * 256 + tid;
        int d = idx >> 8, k = idx & 255;
        W1t[k][d] = W1[idx];
    }
    #pragma unroll
    for (int t = 0; t < 8; ++t) {
        int idx = t * 256 + tid;
        int r = idx >> 8, k = idx & 255;
        seqs[r][k] = seq[(i0 + r) * IN_DIM + k];
    }
    __syncthreads();

    const int r = tid >> 5, d = tid & 31;
    float acc = b1[d];
    #pragma unroll 8
    for (int k = 0; k < IN_DIM; ++k)
        acc = fmaf(seqs[r][k], W1t[k][d], acc);

    const int j = i0 + r;
    g_xT[d * LL + j] = acc;

    // A-fragment emit: pair (d, d^1) via shuffle; even lanes write packed hi/lo
    float pv = __shfl_xor_sync(0xffffffffu, acc, 1);
    if (!(d & 1)) {
        __nv_bfloat16 h0, l0, h1, l1;
        split_bf(acc, h0, l0);
        split_bf(pv,  h1, l1);
        const int mt = j >> 4, jr = j & 15;
        const int ks = d >> 4, kc = d & 15;
        const int lane = (jr & 7) * 4 + ((kc >> 1) & 3);
        const int reg  = (jr >> 3) | ((kc >> 3) << 1);
        const int idx  = ((mt * 2 + ks) * 32 + lane) * 4 + reg;
        g_Af_hi[idx] = pack_bf(h0, h1);
        g_Af_lo[idx] = pack_bf(l0, l1);
    }
}

// ---------------------------------------------------------------------------
// Kernel B: T[i][c][p] = sum_d x[i][d] * W2[p][c*32+d]; emits B-fragments only
// grid (8 cp-tiles of 256, 16 i-tiles of 32), block 256, thread tile 4i x 8cp.
// ---------------------------------------------------------------------------
__global__ void __launch_bounds__(256) k_proj2(const float* __restrict__ W2) {
    __shared__ __align__(16) float ws[DM][256];  // [k][cp_local]
    __shared__ __align__(16) float xs[DM][32];   // [k][i_local]
    const int tid = threadIdx.x;
    const int cp0 = blockIdx.x * 256;
    const int i0  = blockIdx.y * 32;

    #pragma unroll
    for (int t = 0; t < 32; ++t) {
        int idx = t * 256 + tid;
        int cpl = idx >> 5, k = idx & 31;
        int cp = cp0 + cpl;
        ws[k][cpl] = W2[(cp & 63) * 1024 + (cp >> 6) * 32 + k];
    }
    #pragma unroll
    for (int t = 0; t < 4; ++t) {
        int idx = t * 256 + tid;
        int k = idx >> 5, il = idx & 31;
        xs[k][il] = g_xT[k * LL + i0 + il];
    }
    __syncthreads();

    const int cg = tid & 31;   // 8 consecutive cp per thread
    const int ig = tid >> 5;   // 4 consecutive i per thread
    float acc[4][8];
    #pragma unroll
    for (int a = 0; a < 4; ++a)
        #pragma unroll
        for (int b = 0; b < 8; ++b) acc[a][b] = 0.f;

    #pragma unroll 4
    for (int k = 0; k < DM; ++k) {
        float4 xv = *(const float4*)&xs[k][ig * 4];
        float4 wa = *(const float4*)&ws[k][cg * 8];
        float4 wb = *(const float4*)&ws[k][cg * 8 + 4];
        float xr[4] = {xv.x, xv.y, xv.z, xv.w};
        float wv[8] = {wa.x, wa.y, wa.z, wa.w, wb.x, wb.y, wb.z, wb.w};
        #pragma unroll
        for (int a = 0; a < 4; ++a)
            #pragma unroll
            for (int b = 0; b < 8; ++b)
                acc[a][b] = fmaf(xr[a], wv[b], acc[a][b]);
    }

    // B-fragment emit: thread has cp = cp0 + cg*8 + b  ->  c = bx*4 + (cg>>3),
    // p = (cg&7)*8 + b. Partner lane (cg^8) holds c^1 at same (i,p).
    const int cbase = blockIdx.x * 4 + (cg >> 3);   // this thread's c
    const bool even = ((cg >> 3) & 1) == 0;
    const int nt = cg & 7;                           // p>>3
    #pragma unroll
    for (int a = 0; a < 4; ++a) {
        const int i = i0 + ig * 4 + a;
        unsigned* bh = g_Bf_hi + i * 1024;
        unsigned* bl = g_Bf_lo + i * 1024;
        #pragma unroll
        for (int b = 0; b < 8; ++b) {
            float v  = acc[a][b];
            float pv = __shfl_xor_sync(0xffffffffu, v, 8);
            if (even) {
                __nv_bfloat16 h0, l0, h1, l1;
                split_bf(v,  h0, l0);   // c   (even)
                split_bf(pv, h1, l1);   // c+1
                const int ks = cbase >> 4, kc = cbase & 15;
                const int lanef = b * 4 + ((kc >> 1) & 3);
                const int reg   = kc >> 3;
                const int bidx  = ((nt * 2 + ks) * 32 + lanef) * 2 + reg;
                bh[bidx] = pack_bf(h0, h1);
                bl[bidx] = pack_bf(l0, l1);
            }
        }
    }
}

// ---------------------------------------------------------------------------
// Kernel C (HMMA): out[i][j][p] = b2[p] + sum_c x[j][c] * T[i][c][p]
// grid (2 j-tiles of 256, 512 i), 256 threads (8 warps, each 32 j x 64 p).
// D = Ah*Bh + Ah*Bl + Al*Bh in fp32 via mma.sync m16n8k16 bf16.
// ---------------------------------------------------------------------------
#define MMA_BF16(C, A, B)                                                      \
    asm volatile("mma.sync.aligned.m16n8k16.row.col.f32.bf16.bf16.f32 "        \
                 "{%0,%1,%2,%3}, {%4,%5,%6,%7}, {%8,%9}, {%0,%1,%2,%3};"       \
                 : "+f"((C)[0]), "+f"((C)[1]), "+f"((C)[2]), "+f"((C)[3])      \
                 : "r"((A).x), "r"((A).y), "r"((A).z), "r"((A).w),             \
                   "r"((B).x), "r"((B).y))

__global__ void __launch_bounds__(256) k_mma(const float* __restrict__ b2,
                                             float* __restrict__ out) {
    const int tid = threadIdx.x;
    const int w = tid >> 5, l = tid & 31;
    const int gid = l >> 2, q = l & 3;
    const int i  = blockIdx.y;
    const int jt = blockIdx.x;

    float acc[2][8][4];
    #pragma unroll
    for (int nt = 0; nt < 8; ++nt) {
        float2 bb = *(const float2*)(b2 + nt * 8 + 2 * q);
        #pragma unroll
        for (int m = 0; m < 2; ++m) {
            acc[m][nt][0] = bb.x; acc[m][nt][1] = bb.y;
            acc[m][nt][2] = bb.x; acc[m][nt][3] = bb.y;
        }
    }

    const unsigned* __restrict__ bfh = g_Bf_hi + i * 1024;
    const unsigned* __restrict__ bfl = g_Bf_lo + i * 1024;

    #pragma unroll
    for (int ks = 0; ks < 2; ++ks) {
        uint4 Ah[2], Al[2];
        #pragma unroll
        for (int m = 0; m < 2; ++m) {
            const int mt  = jt * 16 + w * 2 + m;
            const int off = ((mt * 2 + ks) * 32 + l) * 4;
            Ah[m] = *(const uint4*)(g_Af_hi + off);
            Al[m] = *(const uint4*)(g_Af_lo + off);
        }
        uint2 Bh[8], Bl[8];
        #pragma unroll
        for (int nt = 0; nt < 8; ++nt) {
            const int off = ((nt * 2 + ks) * 32 + l) * 2;
            Bh[nt] = *(const uint2*)(bfh + off);
            Bl[nt] = *(const uint2*)(bfl + off);
        }
        #pragma unroll
        for (int m = 0; m < 2; ++m)
            #pragma unroll
            for (int nt = 0; nt < 8; ++nt) {
                MMA_BF16(acc[m][nt], Ah[m], Bh[nt]);
                MMA_BF16(acc[m][nt], Ah[m], Bl[nt]);
                MMA_BF16(acc[m][nt], Al[m], Bh[nt]);
            }
    }

    // Epilogue: lane stores float2 pairs; each 4-lane group = one 32B sector.
    float* rowbase = out + ((size_t)i * LL + jt * 256 + w * 32) * PD;
    #pragma unroll
    for (int m = 0; m < 2; ++m)
        #pragma unroll
        for (int nt = 0; nt < 8; ++nt) {
            float* d0 = rowbase + (m * 16 + gid) * PD + nt * 8 + 2 * q;
            *(float2*)d0            = make_float2(acc[m][nt][0], acc[m][nt][1]);
            *(float2*)(d0 + 8 * PD) = make_float2(acc[m][nt][2], acc[m][nt][3]);
        }
}

// ---------------------------------------------------------------------------
extern "C" void kernel_launch(void* const* d_in, const int* in_sizes, int n_in,
                              void* d_out, int out_size) {
    const float* seq = (const float*)d_in[0];
    const float* W1  = (const float*)d_in[1];
    const float* b1  = (const float*)d_in[2];
    const float* W2  = (const float*)d_in[3];
    const float* b2  = (const float*)d_in[4];
    float* out = (float*)d_out;

    k_proj1<<<64, 256>>>(seq, W1, b1);
    k_proj2<<<dim3(8, 16), 256>>>(W2);
    k_mma<<<dim3(2, 512), 256>>>(b2, out);
}

// round 7
// speedup vs baseline: 1.3092x; 1.0562x over previous
#include <cuda_runtime.h>
#include <cuda_bf16.h>
#include <cstdint>

#define LL 512
#define IN_DIM 256
#define DM 32      // dim_msa (contraction dims c and d)
#define PD 64      // pairwise dim
#define CP 2048    // DM*PD
#define IPB 4      // i's per CTA in k_mma

// ---------------------------------------------------------------------------
// Global scratch. mma.sync fragment layouts:
//   g_Af_*[ ((mt*2+ks)*32 + lane)*4 + reg ]   mt=j>>4 (32), ks=c>>4 (2)
//   g_Bf_*[ i*1024 + ((nt*2+ks)*32 + lane)*2 + reg ]  nt=p>>3 (8)
// ---------------------------------------------------------------------------
__device__ __align__(16) unsigned g_Af_hi[8192];
__device__ __align__(16) unsigned g_Af_lo[8192];
__device__ __align__(16) unsigned g_Bf_hi[512 * 1024];
__device__ __align__(16) unsigned g_Bf_lo[512 * 1024];
__device__ float g_xT[DM * LL];          // x transposed: [d][i]

__device__ __forceinline__ unsigned pack_bf(__nv_bfloat16 lo16, __nv_bfloat16 hi16) {
    return (unsigned)__bfloat16_as_ushort(lo16) |
           ((unsigned)__bfloat16_as_ushort(hi16) << 16);
}
__device__ __forceinline__ void split_bf(float f, __nv_bfloat16& h, __nv_bfloat16& l) {
    h = __float2bfloat16(f);
    l = __float2bfloat16(f - __bfloat162float(h));
}

// ---------------------------------------------------------------------------
// Kernel A: x = seq @ W1^T + b1; emits g_xT + A-fragments (hi/lo).
// grid 64 x block 256; 8 rows/block; 4 accumulator chains, vector LDS.
// ---------------------------------------------------------------------------
#define W1PAD 260
__global__ void __launch_bounds__(256) k_proj1(const float* __restrict__ seq,
                                               const float* __restrict__ W1,
                                               const float* __restrict__ b1) {
    __shared__ __align__(16) float W1s[DM][W1PAD];   // [d][k], padded
    __shared__ __align__(16) float seqs[8][IN_DIM];
    const int tid = threadIdx.x;
    const int i0 = blockIdx.x * 8;

    // W1 [32][256] -> W1s, float4 (2048 float4)
    #pragma unroll
    for (int t = 0; t < 8; ++t) {
        int idx4 = t * 256 + tid;
        int d = idx4 >> 6, k4 = idx4 & 63;
        *(float4*)&W1s[d][k4 * 4] = ((const float4*)W1)[idx4];
    }
    // seq rows i0..i0+7 (512 float4)
    #pragma unroll
    for (int t = 0; t < 2; ++t) {
        int idx4 = t * 256 + tid;
        int r = idx4 >> 6, k4 = idx4 & 63;
        *(float4*)&seqs[r][k4 * 4] = ((const float4*)seq)[(i0 + r) * 64 + k4];
    }
    __syncthreads();

    const int r = tid >> 5, d = tid & 31;
    float a0 = 0.f, a1 = 0.f, a2 = 0.f, a3 = 0.f;
    #pragma unroll 8
    for (int k4 = 0; k4 < 64; ++k4) {
        float4 w = *(const float4*)&W1s[d][k4 * 4];
        float4 s = *(const float4*)&seqs[r][k4 * 4];
        a0 = fmaf(s.x, w.x, a0);
        a1 = fmaf(s.y, w.y, a1);
        a2 = fmaf(s.z, w.z, a2);
        a3 = fmaf(s.w, w.w, a3);
    }
    float acc = b1[d] + ((a0 + a1) + (a2 + a3));

    const int j = i0 + r;
    g_xT[d * LL + j] = acc;

    // A-fragment emit: pair (d, d^1) via shuffle; even lanes write packed hi/lo
    float pv = __shfl_xor_sync(0xffffffffu, acc, 1);
    if (!(d & 1)) {
        __nv_bfloat16 h0, l0, h1, l1;
        split_bf(acc, h0, l0);
        split_bf(pv,  h1, l1);
        const int mt = j >> 4, jr = j & 15;
        const int ks = d >> 4, kc = d & 15;
        const int lane = (jr & 7) * 4 + ((kc >> 1) & 3);
        const int reg  = (jr >> 3) | ((kc >> 3) << 1);
        const int idx  = ((mt * 2 + ks) * 32 + lane) * 4 + reg;
        g_Af_hi[idx] = pack_bf(h0, h1);
        g_Af_lo[idx] = pack_bf(l0, l1);
    }
}

// ---------------------------------------------------------------------------
// Kernel B: T[i][c][p] = sum_d x[i][d] * W2[p][c*32+d]; emits B-fragments.
// grid (8 cp-tiles, 16 i-tiles), block 256.  [unchanged, validated]
// ---------------------------------------------------------------------------
__global__ void __launch_bounds__(256) k_proj2(const float* __restrict__ W2) {
    __shared__ __align__(16) float ws[DM][256];
    __shared__ __align__(16) float xs[DM][32];
    const int tid = threadIdx.x;
    const int cp0 = blockIdx.x * 256;
    const int i0  = blockIdx.y * 32;

    #pragma unroll
    for (int t = 0; t < 32; ++t) {
        int idx = t * 256 + tid;
        int cpl = idx >> 5, k = idx & 31;
        int cp = cp0 + cpl;
        ws[k][cpl] = W2[(cp & 63) * 1024 + (cp >> 6) * 32 + k];
    }
    #pragma unroll
    for (int t = 0; t < 4; ++t) {
        int idx = t * 256 + tid;
        int k = idx >> 5, il = idx & 31;
        xs[k][il] = g_xT[k * LL + i0 + il];
    }
    __syncthreads();

    const int cg = tid & 31;
    const int ig = tid >> 5;
    float acc[4][8];
    #pragma unroll
    for (int a = 0; a < 4; ++a)
        #pragma unroll
        for (int b = 0; b < 8; ++b) acc[a][b] = 0.f;

    #pragma unroll 4
    for (int k = 0; k < DM; ++k) {
        float4 xv = *(const float4*)&xs[k][ig * 4];
        float4 wa = *(const float4*)&ws[k][cg * 8];
        float4 wb = *(const float4*)&ws[k][cg * 8 + 4];
        float xr[4] = {xv.x, xv.y, xv.z, xv.w};
        float wv[8] = {wa.x, wa.y, wa.z, wa.w, wb.x, wb.y, wb.z, wb.w};
        #pragma unroll
        for (int a = 0; a < 4; ++a)
            #pragma unroll
            for (int b = 0; b < 8; ++b)
                acc[a][b] = fmaf(xr[a], wv[b], acc[a][b]);
    }

    const int cbase = blockIdx.x * 4 + (cg >> 3);
    const bool even = ((cg >> 3) & 1) == 0;
    const int nt = cg & 7;
    #pragma unroll
    for (int a = 0; a < 4; ++a) {
        const int i = i0 + ig * 4 + a;
        unsigned* bh = g_Bf_hi + i * 1024;
        unsigned* bl = g_Bf_lo + i * 1024;
        #pragma unroll
        for (int b = 0; b < 8; ++b) {
            float v  = acc[a][b];
            float pv = __shfl_xor_sync(0xffffffffu, v, 8);
            if (even) {
                __nv_bfloat16 h0, l0, h1, l1;
                split_bf(v,  h0, l0);
                split_bf(pv, h1, l1);
                const int ks = cbase >> 4, kc = cbase & 15;
                const int lanef = b * 4 + ((kc >> 1) & 3);
                const int reg   = kc >> 3;
                const int bidx  = ((nt * 2 + ks) * 32 + lanef) * 2 + reg;
                bh[bidx] = pack_bf(h0, h1);
                bl[bidx] = pack_bf(l0, l1);
            }
        }
    }
}

// ---------------------------------------------------------------------------
// Kernel C (HMMA): out[i][j][p] = b2[p] + sum_c x[j][c] * T[i][c][p]
// grid (2 jt, 128 ib); block 256 (8 warps, each 32 j x 64 p); IPB=4 i's/CTA.
// A-frags in regs (i-independent); B-frags cp.async double-buffered in smem.
// ---------------------------------------------------------------------------
#define MMA_BF16(C, A, B)                                                      \
    asm volatile("mma.sync.aligned.m16n8k16.row.col.f32.bf16.bf16.f32 "        \
                 "{%0,%1,%2,%3}, {%4,%5,%6,%7}, {%8,%9}, {%0,%1,%2,%3};"       \
                 : "+f"((C)[0]), "+f"((C)[1]), "+f"((C)[2]), "+f"((C)[3])      \
                 : "r"((A).x), "r"((A).y), "r"((A).z), "r"((A).w),             \
                   "r"((B).x), "r"((B).y))

__device__ __forceinline__ uint32_t smem_u32(const void* p) {
    uint32_t a;
    asm("{ .reg .u64 t; cvta.to.shared.u64 t, %1; cvt.u32.u64 %0, t; }"
        : "=r"(a) : "l"(p));
    return a;
}
__device__ __forceinline__ void cp_async16(uint32_t dst, const void* src) {
    asm volatile("cp.async.cg.shared.global [%0], [%1], 16;"
                 :: "r"(dst), "l"(src) : "memory");
}
__device__ __forceinline__ void cp_commit() {
    asm volatile("cp.async.commit_group;" ::: "memory");
}
template <int N>
__device__ __forceinline__ void cp_wait() {
    asm volatile("cp.async.wait_group %0;" :: "n"(N) : "memory");
}

__global__ void __launch_bounds__(256) k_mma(const float* __restrict__ b2,
                                             float* __restrict__ out) {
    // stage layout: [buf][ hi 1024 u32 | lo 1024 u32 ]
    __shared__ __align__(16) unsigned smB[2][2048];

    const int tid = threadIdx.x;
    const int w = tid >> 5, l = tid & 31;
    const int gid = l >> 2, q = l & 3;
    const int jt = blockIdx.x;
    const int ibase = blockIdx.y * IPB;

    // --- A fragments once per CTA (i-independent) ---
    uint4 Ah[2][2], Al[2][2];   // [ks][m]
    #pragma unroll
    for (int ks = 0; ks < 2; ++ks)
        #pragma unroll
        for (int m = 0; m < 2; ++m) {
            const int mt  = jt * 16 + w * 2 + m;
            const int off = ((mt * 2 + ks) * 32 + l) * 4;
            Ah[ks][m] = *(const uint4*)(g_Af_hi + off);
            Al[ks][m] = *(const uint4*)(g_Af_lo + off);
        }

    // --- bias per lane ---
    float2 bb[8];
    #pragma unroll
    for (int nt = 0; nt < 8; ++nt)
        bb[nt] = *(const float2*)(b2 + nt * 8 + 2 * q);

    // --- prefetch stage 0 ---
    const uint32_t smb = smem_u32(&smB[0][0]);
    {   // 512 x 16B per stage: 256 threads x (1 hi + 1 lo)
        const int i = ibase;
        cp_async16(smb + tid * 16,        (const uint4*)(g_Bf_hi + i * 1024) + tid);
        cp_async16(smb + 4096 + tid * 16, (const uint4*)(g_Bf_lo + i * 1024) + tid);
        cp_commit();
    }

    for (int t = 0; t < IPB; ++t) {
        if (t > 0) __syncthreads();          // buffer (t+1)&1 free (compute t-1 done)
        if (t + 1 < IPB) {
            const int i = ibase + t + 1;
            const uint32_t dst = smb + ((t + 1) & 1) * 8192;
            cp_async16(dst + tid * 16,        (const uint4*)(g_Bf_hi + i * 1024) + tid);
            cp_async16(dst + 4096 + tid * 16, (const uint4*)(g_Bf_lo + i * 1024) + tid);
            cp_commit();
            cp_wait<1>();
        } else {
            cp_wait<0>();
        }
        __syncthreads();                     // stage t visible to all

        const unsigned* bh = &smB[t & 1][0];
        const unsigned* bl = &smB[t & 1][1024];

        float acc[2][8][4];
        #pragma unroll
        for (int nt = 0; nt < 8; ++nt)
            #pragma unroll
            for (int m = 0; m < 2; ++m) {
                acc[m][nt][0] = bb[nt].x; acc[m][nt][1] = bb[nt].y;
                acc[m][nt][2] = bb[nt].x; acc[m][nt][3] = bb[nt].y;
            }

        #pragma unroll
        for (int nt = 0; nt < 8; ++nt)
            #pragma unroll
            for (int ks = 0; ks < 2; ++ks) {
                const int off = ((nt * 2 + ks) * 32 + l) * 2;
                uint2 Bh = *(const uint2*)(bh + off);
                uint2 Bl = *(const uint2*)(bl + off);
                #pragma unroll
                for (int m = 0; m < 2; ++m) {
                    MMA_BF16(acc[m][nt], Ah[ks][m], Bh);
                    MMA_BF16(acc[m][nt], Ah[ks][m], Bl);
                    MMA_BF16(acc[m][nt], Al[ks][m], Bh);
                }
            }

        // epilogue: each 4-lane group writes contiguous 32B sectors
        const int i = ibase + t;
        float* rowbase = out + ((size_t)i * LL + jt * 256 + w * 32) * PD;
        #pragma unroll
        for (int m = 0; m < 2; ++m)
            #pragma unroll
            for (int nt = 0; nt < 8; ++nt) {
                float* d0 = rowbase + (m * 16 + gid) * PD + nt * 8 + 2 * q;
                *(float2*)d0            = make_float2(acc[m][nt][0], acc[m][nt][1]);
                *(float2*)(d0 + 8 * PD) = make_float2(acc[m][nt][2], acc[m][nt][3]);
            }
    }
}

// ---------------------------------------------------------------------------
extern "C" void kernel_launch(void* const* d_in, const int* in_sizes, int n_in,
                              void* d_out, int out_size) {
    const float* seq = (const float*)d_in[0];
    const float* W1  = (const float*)d_in[1];
    const float* b1  = (const float*)d_in[2];
    const float* W2  = (const float*)d_in[3];
    const float* b2  = (const float*)d_in[4];
    float* out = (float*)d_out;

    k_proj1<<<64, 256>>>(seq, W1, b1);
    k_proj2<<<dim3(8, 16), 256>>>(W2);
    k_mma<<<dim3(2, LL / IPB), 256>>>(b2, out);
}

// round 8
// speedup vs baseline: 1.4024x; 1.0712x over previous
#include <cuda_runtime.h>
#include <cuda_bf16.h>
#include <cstdint>

#define LL 512
#define IN_DIM 256
#define DM 32      // dim_msa (contraction dims c and d)
#define PD 64      // pairwise dim
#define CP 2048    // DM*PD
#define IPB 4      // i's per CTA in k_mma

// ---------------------------------------------------------------------------
// Global scratch. mma.sync fragment layouts:
//   g_Af_*[ ((mt*2+ks)*32 + lane)*4 + reg ]   mt=j>>4 (32), ks=c>>4 (2)
//   g_Bf_*[ i*1024 + ((nt*2+ks)*32 + lane)*2 + reg ]  nt=p>>3 (8)
// ---------------------------------------------------------------------------
__device__ __align__(16) unsigned g_Af_hi[8192];
__device__ __align__(16) unsigned g_Af_lo[8192];
__device__ __align__(16) unsigned g_Bf_hi[512 * 1024];
__device__ __align__(16) unsigned g_Bf_lo[512 * 1024];
__device__ float g_xT[DM * LL];          // x transposed: [d][i]

__device__ __forceinline__ unsigned pack_bf(__nv_bfloat16 lo16, __nv_bfloat16 hi16) {
    return (unsigned)__bfloat16_as_ushort(lo16) |
           ((unsigned)__bfloat16_as_ushort(hi16) << 16);
}
__device__ __forceinline__ void split_bf(float f, __nv_bfloat16& h, __nv_bfloat16& l) {
    h = __float2bfloat16(f);
    l = __float2bfloat16(f - __bfloat162float(h));
}

// ---------------------------------------------------------------------------
// Kernel A v3: x = seq @ W1^T + b1; emits g_xT + A-fragments (hi/lo).
// grid 128 x block 128; CTA = 4 rows. Thread (kc,d) computes partials for ALL
// 4 rows sharing each W1 smem read; cross-warp reduce over kc via smem.
// ---------------------------------------------------------------------------
#define W1PAD 260
__global__ void __launch_bounds__(128) k_proj1(const float* __restrict__ seq,
                                               const float* __restrict__ W1,
                                               const float* __restrict__ b1) {
    __shared__ __align__(16) float W1s[DM][W1PAD];   // ~33 KB
    __shared__ __align__(16) float seqs[4][IN_DIM];  // 4 KB
    __shared__ __align__(16) float red[4][4][32];    // [r][kc][d] 2 KB
    const int tid = threadIdx.x;
    const int i0 = blockIdx.x * 4;

    // W1 [32][256] -> W1s (2048 float4, 16 per thread)
    #pragma unroll
    for (int t = 0; t < 16; ++t) {
        int idx4 = t * 128 + tid;
        int d = idx4 >> 6, k4 = idx4 & 63;
        *(float4*)&W1s[d][k4 * 4] = ((const float4*)W1)[idx4];
    }
    // seq rows i0..i0+3 (256 float4, 2 per thread)
    #pragma unroll
    for (int t = 0; t < 2; ++t) {
        int idx4 = t * 128 + tid;
        int r = idx4 >> 6, k4 = idx4 & 63;
        *(float4*)&seqs[r][k4 * 4] = ((const float4*)seq)[(i0 + r) * 64 + k4];
    }
    __syncthreads();

    const int d  = tid & 31;
    const int kc = tid >> 5;            // 4 chunks of 64 k
    float acc[4][4];
    #pragma unroll
    for (int r = 0; r < 4; ++r)
        #pragma unroll
        for (int e = 0; e < 4; ++e) acc[r][e] = 0.f;

    #pragma unroll
    for (int i4 = 0; i4 < 16; ++i4) {
        float4 wv = *(const float4*)&W1s[d][kc * 64 + i4 * 4];
        #pragma unroll
        for (int r = 0; r < 4; ++r) {
            float4 s = *(const float4*)&seqs[r][kc * 64 + i4 * 4];  // broadcast
            acc[r][0] = fmaf(s.x, wv.x, acc[r][0]);
            acc[r][1] = fmaf(s.y, wv.y, acc[r][1]);
            acc[r][2] = fmaf(s.z, wv.z, acc[r][2]);
            acc[r][3] = fmaf(s.w, wv.w, acc[r][3]);
        }
    }
    #pragma unroll
    for (int r = 0; r < 4; ++r)
        red[r][kc][d] = (acc[r][0] + acc[r][1]) + (acc[r][2] + acc[r][3]);
    __syncthreads();

    const int rr = tid >> 5, dd = tid & 31;
    float a = (red[rr][0][dd] + red[rr][1][dd]) +
              (red[rr][2][dd] + red[rr][3][dd]) + b1[dd];

    const int j = i0 + rr;
    g_xT[dd * LL + j] = a;

    // A-fragment emit: pair (dd, dd^1) via shuffle; even lanes write hi/lo
    float pv = __shfl_xor_sync(0xffffffffu, a, 1);
    if (!(dd & 1)) {
        __nv_bfloat16 h0, l0, h1, l1;
        split_bf(a,  h0, l0);
        split_bf(pv, h1, l1);
        const int mt = j >> 4, jr = j & 15;
        const int ks = dd >> 4, kcx = dd & 15;
        const int lane = (jr & 7) * 4 + ((kcx >> 1) & 3);
        const int reg  = (jr >> 3) | ((kcx >> 3) << 1);
        const int idx  = ((mt * 2 + ks) * 32 + lane) * 4 + reg;
        g_Af_hi[idx] = pack_bf(h0, h1);
        g_Af_lo[idx] = pack_bf(l0, l1);
    }
}

// ---------------------------------------------------------------------------
// Kernel B: T[i][c][p] = sum_d x[i][d] * W2[p][c*32+d]; emits B-fragments.
// grid (8 cp-tiles, 16 i-tiles), block 256.  [unchanged, validated]
// ---------------------------------------------------------------------------
__global__ void __launch_bounds__(256) k_proj2(const float* __restrict__ W2) {
    __shared__ __align__(16) float ws[DM][256];
    __shared__ __align__(16) float xs[DM][32];
    const int tid = threadIdx.x;
    const int cp0 = blockIdx.x * 256;
    const int i0  = blockIdx.y * 32;

    #pragma unroll
    for (int t = 0; t < 32; ++t) {
        int idx = t * 256 + tid;
        int cpl = idx >> 5, k = idx & 31;
        int cp = cp0 + cpl;
        ws[k][cpl] = W2[(cp & 63) * 1024 + (cp >> 6) * 32 + k];
    }
    #pragma unroll
    for (int t = 0; t < 4; ++t) {
        int idx = t * 256 + tid;
        int k = idx >> 5, il = idx & 31;
        xs[k][il] = g_xT[k * LL + i0 + il];
    }
    __syncthreads();

    const int cg = tid & 31;
    const int ig = tid >> 5;
    float acc[4][8];
    #pragma unroll
    for (int a = 0; a < 4; ++a)
        #pragma unroll
        for (int b = 0; b < 8; ++b) acc[a][b] = 0.f;

    #pragma unroll 4
    for (int k = 0; k < DM; ++k) {
        float4 xv = *(const float4*)&xs[k][ig * 4];
        float4 wa = *(const float4*)&ws[k][cg * 8];
        float4 wb = *(const float4*)&ws[k][cg * 8 + 4];
        float xr[4] = {xv.x, xv.y, xv.z, xv.w};
        float wv[8] = {wa.x, wa.y, wa.z, wa.w, wb.x, wb.y, wb.z, wb.w};
        #pragma unroll
        for (int a = 0; a < 4; ++a)
            #pragma unroll
            for (int b = 0; b < 8; ++b)
                acc[a][b] = fmaf(xr[a], wv[b], acc[a][b]);
    }

    const int cbase = blockIdx.x * 4 + (cg >> 3);
    const bool even = ((cg >> 3) & 1) == 0;
    const int nt = cg & 7;
    #pragma unroll
    for (int a = 0; a < 4; ++a) {
        const int i = i0 + ig * 4 + a;
        unsigned* bh = g_Bf_hi + i * 1024;
        unsigned* bl = g_Bf_lo + i * 1024;
        #pragma unroll
        for (int b = 0; b < 8; ++b) {
            float v  = acc[a][b];
            float pv = __shfl_xor_sync(0xffffffffu, v, 8);
            if (even) {
                __nv_bfloat16 h0, l0, h1, l1;
                split_bf(v,  h0, l0);
                split_bf(pv, h1, l1);
                const int ks = cbase >> 4, kc = cbase & 15;
                const int lanef = b * 4 + ((kc >> 1) & 3);
                const int reg   = kc >> 3;
                const int bidx  = ((nt * 2 + ks) * 32 + lanef) * 2 + reg;
                bh[bidx] = pack_bf(h0, h1);
                bl[bidx] = pack_bf(l0, l1);
            }
        }
    }
}

// ---------------------------------------------------------------------------
// Kernel C (HMMA v4): out[i][j][p] = b2[p] + sum_c x[j][c] * T[i][c][p]
// grid (2 jt, 128 ib); block 256; forced 2 CTAs/SM. nt processed in two
// halves (acc 32 regs live); bias via smem; B-frags cp.async double-buffered.
// ---------------------------------------------------------------------------
#define MMA_BF16(C, A, B)                                                      \
    asm volatile("mma.sync.aligned.m16n8k16.row.col.f32.bf16.bf16.f32 "        \
                 "{%0,%1,%2,%3}, {%4,%5,%6,%7}, {%8,%9}, {%0,%1,%2,%3};"       \
                 : "+f"((C)[0]), "+f"((C)[1]), "+f"((C)[2]), "+f"((C)[3])      \
                 : "r"((A).x), "r"((A).y), "r"((A).z), "r"((A).w),             \
                   "r"((B).x), "r"((B).y))

__device__ __forceinline__ uint32_t smem_u32(const void* p) {
    uint32_t a;
    asm("{ .reg .u64 t; cvta.to.shared.u64 t, %1; cvt.u32.u64 %0, t; }"
        : "=r"(a) : "l"(p));
    return a;
}
__device__ __forceinline__ void cp_async16(uint32_t dst, const void* src) {
    asm volatile("cp.async.cg.shared.global [%0], [%1], 16;"
                 :: "r"(dst), "l"(src) : "memory");
}
__device__ __forceinline__ void cp_commit() {
    asm volatile("cp.async.commit_group;" ::: "memory");
}
template <int N>
__device__ __forceinline__ void cp_wait() {
    asm volatile("cp.async.wait_group %0;" :: "n"(N) : "memory");
}

__global__ void __launch_bounds__(256, 2) k_mma(const float* __restrict__ b2,
                                                float* __restrict__ out) {
    __shared__ __align__(16) unsigned smB[2][2048];   // 16 KB
    __shared__ __align__(16) float smBias[64];

    const int tid = threadIdx.x;
    const int w = tid >> 5, l = tid & 31;
    const int gid = l >> 2, q = l & 3;
    const int jt = blockIdx.x;
    const int ibase = blockIdx.y * IPB;

    if (tid < 64) smBias[tid] = b2[tid];

    // A fragments in registers, once per CTA (i-independent)
    uint4 Ah[2][2], Al[2][2];   // [ks][m]
    #pragma unroll
    for (int ks = 0; ks < 2; ++ks)
        #pragma unroll
        for (int m = 0; m < 2; ++m) {
            const int mt  = jt * 16 + w * 2 + m;
            const int off = ((mt * 2 + ks) * 32 + l) * 4;
            Ah[ks][m] = *(const uint4*)(g_Af_hi + off);
            Al[ks][m] = *(const uint4*)(g_Af_lo + off);
        }

    // prefetch stage 0: 512 x 16B (256 threads x hi+lo)
    const uint32_t smb = smem_u32(&smB[0][0]);
    {
        const int i = ibase;
        cp_async16(smb + tid * 16,        (const uint4*)(g_Bf_hi + i * 1024) + tid);
        cp_async16(smb + 4096 + tid * 16, (const uint4*)(g_Bf_lo + i * 1024) + tid);
        cp_commit();
    }

    for (int t = 0; t < IPB; ++t) {
        if (t > 0) __syncthreads();          // prior compute done on buffer (t+1)&1
        if (t + 1 < IPB) {
            const int i = ibase + t + 1;
            const uint32_t dst = smb + ((t + 1) & 1) * 8192;
            cp_async16(dst + tid * 16,        (const uint4*)(g_Bf_hi + i * 1024) + tid);
            cp_async16(dst + 4096 + tid * 16, (const uint4*)(g_Bf_lo + i * 1024) + tid);
            cp_commit();
            cp_wait<1>();
        } else {
            cp_wait<0>();
        }
        __syncthreads();                     // stage t visible

        const unsigned* bh = &smB[t & 1][0];
        const unsigned* bl = &smB[t & 1][1024];
        float* rowbase = out + ((size_t)(ibase + t) * LL + jt * 256 + w * 32) * PD;

        #pragma unroll 1
        for (int h = 0; h < 2; ++h) {        // nt halves: keeps acc at 32 regs
            float acc[2][4][4];
            #pragma unroll
            for (int m = 0; m < 2; ++m)
                #pragma unroll
                for (int n4 = 0; n4 < 4; ++n4)
                    #pragma unroll
                    for (int e = 0; e < 4; ++e) acc[m][n4][e] = 0.f;

            #pragma unroll
            for (int n4 = 0; n4 < 4; ++n4) {
                const int nt = h * 4 + n4;
                #pragma unroll
                for (int ks = 0; ks < 2; ++ks) {
                    const int off = ((nt * 2 + ks) * 32 + l) * 2;
                    uint2 Bh = *(const uint2*)(bh + off);
                    uint2 Bl = *(const uint2*)(bl + off);
                    #pragma unroll
                    for (int m = 0; m < 2; ++m) {
                        MMA_BF16(acc[m][n4], Ah[ks][m], Bh);
                        MMA_BF16(acc[m][n4], Ah[ks][m], Bl);
                        MMA_BF16(acc[m][n4], Al[ks][m], Bh);
                    }
                }
            }

            // epilogue half: bias from smem; 32B-sector stores
            #pragma unroll
            for (int m = 0; m < 2; ++m)
                #pragma unroll
                for (int n4 = 0; n4 < 4; ++n4) {
                    const int nt = h * 4 + n4;
                    float2 bb = *(const float2*)&smBias[nt * 8 + 2 * q];
                    float* d0 = rowbase + (m * 16 + gid) * PD + nt * 8 + 2 * q;
                    *(float2*)d0 =
                        make_float2(acc[m][n4][0] + bb.x, acc[m][n4][1] + bb.y);
                    *(float2*)(d0 + 8 * PD) =
                        make_float2(acc[m][n4][2] + bb.x, acc[m][n4][3] + bb.y);
                }
        }
    }
}

// ---------------------------------------------------------------------------
extern "C" void kernel_launch(void* const* d_in, const int* in_sizes, int n_in,
                              void* d_out, int out_size) {
    const float* seq = (const float*)d_in[0];
    const float* W1  = (const float*)d_in[1];
    const float* b1  = (const float*)d_in[2];
    const float* W2  = (const float*)d_in[3];
    const float* b2  = (const float*)d_in[4];
    float* out = (float*)d_out;

    k_proj1<<<128, 128>>>(seq, W1, b1);
    k_proj2<<<dim3(8, 16), 256>>>(W2);
    k_mma<<<dim3(2, LL / IPB), 256>>>(b2, out);
}